// round 11
// baseline (speedup 1.0000x reference)
#include <cuda_runtime.h>
#include <cuda_fp16.h>
#include <cstdint>

// Problem constants
#define B_BATCH 8192
#define H_DIM   1024
#define K_TOT   2048

// GEMM tiling: CTA = M128 x N128, 4 warps (2x2), warp tile 64x64, 2 CTAs/SM
#define TM      128
#define NEFF    128
#define KC      64               // K chunk in halves (128B rows)
#define NKT     (K_TOT / KC)     // 32 chunks
#define STAGES  3
#define KCP     72               // padded SMEM row stride in halves (144B)
#define THREADS 128

// SMEM offsets in halves
#define STAGE_HALVES  ((TM + NEFF) * KCP)          // 256*72 = 18432
#define A_OFF(st)     ((st) * STAGE_HALVES)
#define B_OFF(st)     ((st) * STAGE_HALVES + TM * KCP)
#define SMEM_BYTES    (STAGES * STAGE_HALVES * 2)  // 110592 -> 2 CTAs/SM

// fp16 scratch (conversion prologue, each launch)
__device__ __half g_xh[(size_t)B_BATCH * K_TOT];   // [8192, 2048] = [hidden|inputs]
__device__ __half g_wh[(size_t)4 * H_DIM * K_TOT]; // gate-interleaved rows, K-major

#define X_BLOCKS ((B_BATCH * K_TOT / 8) / 256)     // 8192
#define W_BLOCKS ((4 * H_DIM * K_TOT / 8) / 256)   // 4096

__device__ __forceinline__ void mma16816(float* c,
                                         uint32_t a0, uint32_t a1, uint32_t a2, uint32_t a3,
                                         uint32_t b0, uint32_t b1) {
    asm volatile(
        "mma.sync.aligned.m16n8k16.row.col.f32.f16.f16.f32 "
        "{%0,%1,%2,%3}, {%4,%5,%6,%7}, {%8,%9}, {%0,%1,%2,%3};"
        : "+f"(c[0]), "+f"(c[1]), "+f"(c[2]), "+f"(c[3])
        : "r"(a0), "r"(a1), "r"(a2), "r"(a3), "r"(b0), "r"(b1));
}

__device__ __forceinline__ void cp16(uint32_t dst, const void* src) {
    asm volatile("cp.async.cg.shared.global [%0], [%1], 16;" :: "r"(dst), "l"(src));
}

__device__ __forceinline__ uint32_t smem_u32(const void* p) {
    uint32_t a;
    asm("{ .reg .u64 t; cvta.to.shared.u64 t, %1; cvt.u32.u64 %0, t; }" : "=r"(a) : "l"(p));
    return a;
}

__device__ __forceinline__ float sigmoidf_(float x) {
    return 1.0f / (1.0f + __expf(-x));
}

// ---------------- fused fp16 conversion prologue ----------------
// blocks [0, X_BLOCKS): x = [hidden|inputs]; blocks [X_BLOCKS, +W_BLOCKS): W permute
__global__ __launch_bounds__(256) void cvt_all_kernel(const float* __restrict__ hidden,
                                                      const float* __restrict__ inputs,
                                                      const float* __restrict__ Wf,
                                                      const float* __restrict__ Wi,
                                                      const float* __restrict__ Wo,
                                                      const float* __restrict__ Wc) {
    if (blockIdx.x < X_BLOCKS) {
        const size_t i = (size_t)blockIdx.x * blockDim.x + threadIdx.x;
        const size_t base = i * 8;
        const int r = (int)(base >> 11);
        const int c = (int)(base & 2047);
        const float* src = (c < H_DIM) ? (hidden + (size_t)r * H_DIM + c)
                                       : (inputs + (size_t)r * H_DIM + (c - H_DIM));
        float4 v0 = *reinterpret_cast<const float4*>(src);
        float4 v1 = *reinterpret_cast<const float4*>(src + 4);
        __half2 h[4];
        h[0] = __floats2half2_rn(v0.x, v0.y);
        h[1] = __floats2half2_rn(v0.z, v0.w);
        h[2] = __floats2half2_rn(v1.x, v1.y);
        h[3] = __floats2half2_rn(v1.z, v1.w);
        *reinterpret_cast<uint4*>(&g_xh[base]) = *reinterpret_cast<uint4*>(h);
    } else {
        // W rows permuted: each warp's 64 n-cols = 4 gates x 16 h:
        // n = (h>>5)*128 + ((h>>4)&1)*64 + g*16 + (h&15)
        const size_t i = (size_t)(blockIdx.x - X_BLOCKS) * blockDim.x + threadIdx.x;
        const size_t base = i * 8;
        const int g   = (int)(base >> 21);
        const size_t rem = base & ((1u << 21) - 1);
        const int h = (int)(rem >> 11);
        const int k = (int)(rem & 2047);
        const float* wp = (g == 0) ? Wf : (g == 1) ? Wi : (g == 2) ? Wo : Wc;
        const float* src = wp + (size_t)h * K_TOT + k;
        float4 v0 = *reinterpret_cast<const float4*>(src);
        float4 v1 = *reinterpret_cast<const float4*>(src + 4);
        __half2 hh[4];
        hh[0] = __floats2half2_rn(v0.x, v0.y);
        hh[1] = __floats2half2_rn(v0.z, v0.w);
        hh[2] = __floats2half2_rn(v1.x, v1.y);
        hh[3] = __floats2half2_rn(v1.z, v1.w);
        const int n = (h >> 5) * 128 + ((h >> 4) & 1) * 64 + g * 16 + (h & 15);
        *reinterpret_cast<uint4*>(&g_wh[(size_t)n * K_TOT + k]) = *reinterpret_cast<uint4*>(hh);
    }
}

// ---------------- fused GEMM + LSTM epilogue ----------------

__global__ __launch_bounds__(THREADS, 2)
void lstm_cell_kernel(const float* __restrict__ cold_p,
                      const float* __restrict__ bfv, const float* __restrict__ biv,
                      const float* __restrict__ bov, const float* __restrict__ bcv,
                      float* __restrict__ out) {
    extern __shared__ __half sh[];
    const uint32_t sbase = smem_u32(sh);

    const int tid  = threadIdx.x;
    const int lane = tid & 31;
    const int wid  = tid >> 5;
    const int wm   = wid & 1;    // 2 warps along M (64 rows each)
    const int wn   = wid >> 1;   // 2 warps along N_eff (64 each)
    const int m0   = blockIdx.x * TM;
    const int n0   = blockIdx.y * NEFF;
    const int h0   = blockIdx.y * 32;

    const int f  = tid & 7;      // 16B chunk within a 128B row
    const int rb = tid >> 3;     // 0..15

    // acc[i][j][e]: i = m-block (16 rows), j = n-block (8 cols), 64x64 warp tile
    float acc[4][8][4];
    #pragma unroll
    for (int i = 0; i < 4; ++i)
        #pragma unroll
        for (int j = 0; j < 8; ++j)
            #pragma unroll
            for (int e = 0; e < 4; ++e)
                acc[i][j][e] = 0.0f;

#define ISSUE(kt_, st_)                                                                  \
    do {                                                                                 \
        if ((kt_) < NKT) {                                                               \
            const int kb_ = (kt_) * KC;                                                  \
            _Pragma("unroll")                                                            \
            for (int p = 0; p < 8; ++p) {                                                \
                const int r_ = rb + 16 * p;                                              \
                cp16(sbase + 2u * (A_OFF(st_) + r_ * KCP + f * 8),                       \
                     &g_xh[(size_t)(m0 + r_) * K_TOT + kb_ + f * 8]);                    \
            }                                                                            \
            _Pragma("unroll")                                                            \
            for (int p = 0; p < 8; ++p) {                                                \
                const int r_ = rb + 16 * p;                                              \
                cp16(sbase + 2u * (B_OFF(st_) + r_ * KCP + f * 8),                       \
                     &g_wh[(size_t)(n0 + r_) * K_TOT + kb_ + f * 8]);                    \
            }                                                                            \
        }                                                                                \
        asm volatile("cp.async.commit_group;");                                          \
    } while (0)

    const int q  = lane & 3;
    const int nr = lane >> 2;

    // Register fragment double buffers: 32 + 32 regs
    uint32_t af[2][4][4];
    uint32_t bfr[2][8][2];

#define LOAD_FRAGS(st_, s_, bu_)                                                         \
    do {                                                                                 \
        const int kq_ = (s_) * 16 + 2 * q;                                               \
        _Pragma("unroll")                                                                \
        for (int j = 0; j < 8; ++j) {                                                    \
            const __half* bp_ = &sh[B_OFF(st_) + (wn * 64 + j * 8 + nr) * KCP + kq_];    \
            bfr[bu_][j][0] = *reinterpret_cast<const uint32_t*>(bp_);                    \
            bfr[bu_][j][1] = *reinterpret_cast<const uint32_t*>(bp_ + 8);                \
        }                                                                                \
        _Pragma("unroll")                                                                \
        for (int i = 0; i < 4; ++i) {                                                    \
            const __half* ap_ = &sh[A_OFF(st_) + (wm * 64 + i * 16 + nr) * KCP + kq_];   \
            af[bu_][i][0] = *reinterpret_cast<const uint32_t*>(ap_);                     \
            af[bu_][i][1] = *reinterpret_cast<const uint32_t*>(ap_ + 8 * KCP);           \
            af[bu_][i][2] = *reinterpret_cast<const uint32_t*>(ap_ + 8);                 \
            af[bu_][i][3] = *reinterpret_cast<const uint32_t*>(ap_ + 8 * KCP + 8);       \
        }                                                                                \
    } while (0)

#define MMA_STEP(bu_)                                                                    \
    do {                                                                                 \
        _Pragma("unroll")                                                                \
        for (int i = 0; i < 4; ++i)                                                      \
            _Pragma("unroll")                                                            \
            for (int j = 0; j < 8; ++j)                                                  \
                mma16816(acc[i][j], af[bu_][i][0], af[bu_][i][1],                        \
                         af[bu_][i][2], af[bu_][i][3], bfr[bu_][j][0], bfr[bu_][j][1]);  \
    } while (0)

    // ---- 3-stage pipeline, single barrier per chunk, frag double-buffer ----
    ISSUE(0, 0);
    ISSUE(1, 1);

    for (int kt = 0; kt < NKT; ++kt) {
        const int st = kt % STAGES;
        asm volatile("cp.async.wait_group 1;");  // stage kt complete
        __syncthreads();                         // all warps done reading stage kt-1
        ISSUE(kt + 2, (kt + 2) % STAGES);        // refill buffer freed by kt-1

        LOAD_FRAGS(st, 0, 0);
        #pragma unroll
        for (int s = 0; s < 4; ++s) {
            if (s < 3) LOAD_FRAGS(st, s + 1, (s + 1) & 1);
            MMA_STEP(s & 1);
        }
    }

    // ---- fused epilogue (each warp has all 4 gates of its 16-h slice) ----
    const size_t COFF = (size_t)B_BATCH * H_DIM;

    #pragma unroll
    for (int jc = 0; jc < 2; ++jc) {
        const int h = h0 + wn * 16 + jc * 8 + 2 * q;
        const float bF0 = bfv[h], bF1 = bfv[h + 1];
        const float bI0 = biv[h], bI1 = biv[h + 1];
        const float bO0 = bov[h], bO1 = bov[h + 1];
        const float bC0 = bcv[h], bC1 = bcv[h + 1];

        #pragma unroll
        for (int i = 0; i < 4; ++i) {
            #pragma unroll
            for (int hh = 0; hh < 2; ++hh) {
                const int row = m0 + wm * 64 + i * 16 + nr + 8 * hh;
                const int e = hh * 2;

                const float fg0 = sigmoidf_(acc[i][0 + jc][e]     + bF0);
                const float fg1 = sigmoidf_(acc[i][0 + jc][e + 1] + bF1);
                const float ig0 = sigmoidf_(acc[i][2 + jc][e]     + bI0);
                const float ig1 = sigmoidf_(acc[i][2 + jc][e + 1] + bI1);
                const float og0 = sigmoidf_(acc[i][4 + jc][e]     + bO0);
                const float og1 = sigmoidf_(acc[i][4 + jc][e + 1] + bO1);
                const float cg0 = tanhf(acc[i][6 + jc][e]     + bC0);
                const float cg1 = tanhf(acc[i][6 + jc][e + 1] + bC1);

                const float2 co = *reinterpret_cast<const float2*>(
                    cold_p + (size_t)row * H_DIM + h);
                const float cn0 = fg0 * co.x + ig0 * cg0;
                const float cn1 = fg1 * co.y + ig1 * cg1;

                float2 hv; hv.x = og0 * tanhf(cn0); hv.y = og1 * tanhf(cn1);
                float2 cv; cv.x = cn0; cv.y = cn1;

                *reinterpret_cast<float2*>(out + (size_t)row * H_DIM + h)        = hv;
                *reinterpret_cast<float2*>(out + COFF + (size_t)row * H_DIM + h) = cv;
            }
        }
    }
}

extern "C" void kernel_launch(void* const* d_in, const int* in_sizes, int n_in,
                              void* d_out, int out_size) {
    (void)in_sizes; (void)n_in; (void)out_size;
    const float* inputs = (const float*)d_in[0];
    const float* hidden = (const float*)d_in[1];
    const float* c      = (const float*)d_in[2];
    const float* Wf     = (const float*)d_in[3];
    const float* bf     = (const float*)d_in[4];
    const float* Wi     = (const float*)d_in[5];
    const float* bi     = (const float*)d_in[6];
    const float* Wo     = (const float*)d_in[7];
    const float* bo     = (const float*)d_in[8];
    const float* Wc     = (const float*)d_in[9];
    const float* bc     = (const float*)d_in[10];
    float* out = (float*)d_out;

    cvt_all_kernel<<<X_BLOCKS + W_BLOCKS, 256>>>(hidden, inputs, Wf, Wi, Wo, Wc);

    cudaFuncSetAttribute(lstm_cell_kernel,
                         cudaFuncAttributeMaxDynamicSharedMemorySize, SMEM_BYTES);
    dim3 grid(B_BATCH / TM, (4 * H_DIM) / NEFF);  // 64 x 32 = 2048 CTAs
    lstm_cell_kernel<<<grid, THREADS, SMEM_BYTES>>>(c, bf, bi, bo, bc, out);
}

// round 14
// speedup vs baseline: 1.0234x; 1.0234x over previous
#include <cuda_runtime.h>
#include <cuda_fp16.h>
#include <cstdint>

// Problem constants
#define B_BATCH 8192
#define H_DIM   1024
#define K_TOT   2048

// GEMM tiling: CTA = M128 x N128 (32 h-cols x 4 gates), 8 warps, 64x32 warp tile,
// 2 CTAs/SM (R10 config) + cross-chunk fragment pipelining.
#define TM      128
#define NEFF    128
#define KC      64               // K chunk in halves (128B rows)
#define NKT     (K_TOT / KC)     // 32 chunks
#define STAGES  3
#define KCP     72               // padded SMEM row stride in halves (144B)
#define THREADS 256

// SMEM offsets in halves
#define STAGE_HALVES  ((TM + NEFF) * KCP)          // 256*72 = 18432
#define A_OFF(st)     ((st) * STAGE_HALVES)
#define B_OFF(st)     ((st) * STAGE_HALVES + TM * KCP)
#define SMEM_BYTES    (STAGES * STAGE_HALVES * 2)  // 110592 -> 2 CTAs/SM

// fp16 scratch (conversion prologue, each launch)
__device__ __half g_xh[(size_t)B_BATCH * K_TOT];   // [8192, 2048] = [hidden|inputs]
__device__ __half g_wh[(size_t)4 * H_DIM * K_TOT]; // gate-interleaved rows, K-major

#define X_BLOCKS ((B_BATCH * K_TOT / 8) / 256)     // 8192
#define W_BLOCKS ((4 * H_DIM * K_TOT / 8) / 256)   // 4096

__device__ __forceinline__ void mma16816(float* c,
                                         uint32_t a0, uint32_t a1, uint32_t a2, uint32_t a3,
                                         uint32_t b0, uint32_t b1) {
    asm volatile(
        "mma.sync.aligned.m16n8k16.row.col.f32.f16.f16.f32 "
        "{%0,%1,%2,%3}, {%4,%5,%6,%7}, {%8,%9}, {%0,%1,%2,%3};"
        : "+f"(c[0]), "+f"(c[1]), "+f"(c[2]), "+f"(c[3])
        : "r"(a0), "r"(a1), "r"(a2), "r"(a3), "r"(b0), "r"(b1));
}

__device__ __forceinline__ void cp16(uint32_t dst, const void* src) {
    asm volatile("cp.async.cg.shared.global [%0], [%1], 16;" :: "r"(dst), "l"(src));
}

__device__ __forceinline__ uint32_t smem_u32(const void* p) {
    uint32_t a;
    asm("{ .reg .u64 t; cvta.to.shared.u64 t, %1; cvt.u32.u64 %0, t; }" : "=r"(a) : "l"(p));
    return a;
}

__device__ __forceinline__ float sigmoidf_(float x) {
    return 1.0f / (1.0f + __expf(-x));
}

// ---------------- fused fp16 conversion prologue ----------------
// blocks [0, X_BLOCKS): x = [hidden|inputs]; blocks [X_BLOCKS, +W_BLOCKS): W permute
__global__ __launch_bounds__(256) void cvt_all_kernel(const float* __restrict__ hidden,
                                                      const float* __restrict__ inputs,
                                                      const float* __restrict__ Wf,
                                                      const float* __restrict__ Wi,
                                                      const float* __restrict__ Wo,
                                                      const float* __restrict__ Wc) {
    if (blockIdx.x < X_BLOCKS) {
        const size_t i = (size_t)blockIdx.x * blockDim.x + threadIdx.x;
        const size_t base = i * 8;
        const int r = (int)(base >> 11);
        const int c = (int)(base & 2047);
        const float* src = (c < H_DIM) ? (hidden + (size_t)r * H_DIM + c)
                                       : (inputs + (size_t)r * H_DIM + (c - H_DIM));
        float4 v0 = *reinterpret_cast<const float4*>(src);
        float4 v1 = *reinterpret_cast<const float4*>(src + 4);
        __half2 h[4];
        h[0] = __floats2half2_rn(v0.x, v0.y);
        h[1] = __floats2half2_rn(v0.z, v0.w);
        h[2] = __floats2half2_rn(v1.x, v1.y);
        h[3] = __floats2half2_rn(v1.z, v1.w);
        *reinterpret_cast<uint4*>(&g_xh[base]) = *reinterpret_cast<uint4*>(h);
    } else {
        // W rows permuted: n = (h>>5)*128 + ((h>>3)&3)*32 + g*8 + (h&7)
        const size_t i = (size_t)(blockIdx.x - X_BLOCKS) * blockDim.x + threadIdx.x;
        const size_t base = i * 8;
        const int g   = (int)(base >> 21);
        const size_t rem = base & ((1u << 21) - 1);
        const int h = (int)(rem >> 11);
        const int k = (int)(rem & 2047);
        const float* wp = (g == 0) ? Wf : (g == 1) ? Wi : (g == 2) ? Wo : Wc;
        const float* src = wp + (size_t)h * K_TOT + k;
        float4 v0 = *reinterpret_cast<const float4*>(src);
        float4 v1 = *reinterpret_cast<const float4*>(src + 4);
        __half2 hh[4];
        hh[0] = __floats2half2_rn(v0.x, v0.y);
        hh[1] = __floats2half2_rn(v0.z, v0.w);
        hh[2] = __floats2half2_rn(v1.x, v1.y);
        hh[3] = __floats2half2_rn(v1.z, v1.w);
        const int n = (h >> 5) * 128 + ((h >> 3) & 3) * 32 + g * 8 + (h & 7);
        *reinterpret_cast<uint4*>(&g_wh[(size_t)n * K_TOT + k]) = *reinterpret_cast<uint4*>(hh);
    }
}

// ---------------- fused GEMM + LSTM epilogue ----------------

__global__ __launch_bounds__(THREADS, 2)
void lstm_cell_kernel(const float* __restrict__ cold_p,
                      const float* __restrict__ bfv, const float* __restrict__ biv,
                      const float* __restrict__ bov, const float* __restrict__ bcv,
                      float* __restrict__ out) {
    extern __shared__ __half sh[];
    const uint32_t sbase = smem_u32(sh);

    const int tid  = threadIdx.x;
    const int lane = tid & 31;
    const int wid  = tid >> 5;
    const int wm   = wid & 1;    // 2 warps along M (64 rows each)
    const int wn   = wid >> 1;   // 4 warps along N_eff (32 each)
    const int m0   = blockIdx.x * TM;
    const int n0   = blockIdx.y * NEFF;
    const int h0   = blockIdx.y * 32;

    const int f  = tid & 7;      // 16B chunk within a 128B row
    const int rb = tid >> 3;     // 0..31

    // acc[i][j][e]: i = m-block (16 rows), j = gate (8 cols)
    float acc[4][4][4];
    #pragma unroll
    for (int i = 0; i < 4; ++i)
        #pragma unroll
        for (int j = 0; j < 4; ++j)
            #pragma unroll
            for (int e = 0; e < 4; ++e)
                acc[i][j][e] = 0.0f;

#define ISSUE(kt_, st_)                                                                  \
    do {                                                                                 \
        if ((kt_) < NKT) {                                                               \
            const int kb_ = (kt_) * KC;                                                  \
            _Pragma("unroll")                                                            \
            for (int p = 0; p < 4; ++p) {                                                \
                const int r_ = rb + 32 * p;                                              \
                cp16(sbase + 2u * (A_OFF(st_) + r_ * KCP + f * 8),                       \
                     &g_xh[(size_t)(m0 + r_) * K_TOT + kb_ + f * 8]);                    \
            }                                                                            \
            _Pragma("unroll")                                                            \
            for (int p = 0; p < 4; ++p) {                                                \
                const int r_ = rb + 32 * p;                                              \
                cp16(sbase + 2u * (B_OFF(st_) + r_ * KCP + f * 8),                       \
                     &g_wh[(size_t)(n0 + r_) * K_TOT + kb_ + f * 8]);                    \
            }                                                                            \
        }                                                                                \
        asm volatile("cp.async.commit_group;");                                          \
    } while (0)

    const int q  = lane & 3;
    const int nr = lane >> 2;

    // Register fragment double buffers: 32 + 16 regs
    uint32_t af[2][4][4];
    uint32_t bfr[2][4][2];

#define LOAD_FRAGS(st_, s_, bu_)                                                         \
    do {                                                                                 \
        const int kq_ = (s_) * 16 + 2 * q;                                               \
        _Pragma("unroll")                                                                \
        for (int j = 0; j < 4; ++j) {                                                    \
            const __half* bp_ = &sh[B_OFF(st_) + (wn * 32 + j * 8 + nr) * KCP + kq_];    \
            bfr[bu_][j][0] = *reinterpret_cast<const uint32_t*>(bp_);                    \
            bfr[bu_][j][1] = *reinterpret_cast<const uint32_t*>(bp_ + 8);                \
        }                                                                                \
        _Pragma("unroll")                                                                \
        for (int i = 0; i < 4; ++i) {                                                    \
            const __half* ap_ = &sh[A_OFF(st_) + (wm * 64 + i * 16 + nr) * KCP + kq_];   \
            af[bu_][i][0] = *reinterpret_cast<const uint32_t*>(ap_);                     \
            af[bu_][i][1] = *reinterpret_cast<const uint32_t*>(ap_ + 8 * KCP);           \
            af[bu_][i][2] = *reinterpret_cast<const uint32_t*>(ap_ + 8);                 \
            af[bu_][i][3] = *reinterpret_cast<const uint32_t*>(ap_ + 8 * KCP + 8);       \
        }                                                                                \
    } while (0)

#define MMA_STEP(bu_)                                                                    \
    do {                                                                                 \
        _Pragma("unroll")                                                                \
        for (int i = 0; i < 4; ++i)                                                      \
            _Pragma("unroll")                                                            \
            for (int j = 0; j < 4; ++j)                                                  \
                mma16816(acc[i][j], af[bu_][i][0], af[bu_][i][1],                        \
                         af[bu_][i][2], af[bu_][i][3], bfr[bu_][j][0], bfr[bu_][j][1]);  \
    } while (0)

    // ---- 3-stage pipeline, cross-chunk frag prefetch, mid-chunk barrier ----
    //
    // Invariants at top of chunk kt:
    //   * stage kt resident & visible (chunk kt-1's wait_group 0 + barrier)
    //   * step-0 frags of chunk kt already in register buffer 0
    //   * cp.async group for stage kt+1 issued (completes during this chunk)
    // Mid-chunk: wait_group 0 (group kt+1 issued a full chunk ago -> ~free),
    // barrier (every warp past ALL chunk kt-1 reads by program order), then
    // ISSUE(kt+2) safely overwrites stage (kt+2)%3 = (kt-1)%3.
    //
    // Buffer parity: step s lives in register buffer (s & 1):
    //   buf0 = steps 0,2 (+ next chunk's step 0), buf1 = steps 1,3.
    ISSUE(0, 0);
    ISSUE(1, 1);
    asm volatile("cp.async.wait_group 1;");      // stage 0 landed
    __syncthreads();                             // visible to all threads
    LOAD_FRAGS(0, 0, 0);                         // chunk 0, step 0 -> buf0

    for (int kt = 0; kt < NKT; ++kt) {
        const int st  = kt % STAGES;
        const int stn = (kt + 1) % STAGES;

        LOAD_FRAGS(st, 1, 1);                    // step 1 -> buf1
        MMA_STEP(0);                             // consume step 0 (buf0)

        asm volatile("cp.async.wait_group 0;");  // stage kt+1 landed (own groups)
        __syncthreads();                         // all threads past kt-1 reads
        ISSUE(kt + 2, (kt + 2) % STAGES);        // refill stage freed by chunk kt-1

        LOAD_FRAGS(st, 2, 0);                    // step 2 -> buf0
        MMA_STEP(1);                             // consume step 1 (buf1)
        LOAD_FRAGS(st, 3, 1);                    // step 3 -> buf1
        MMA_STEP(0);                             // consume step 2 (buf0)
        LOAD_FRAGS(stn, 0, 0);                   // next chunk step 0 -> buf0
        MMA_STEP(1);                             // consume step 3 (buf1)
    }

    // ---- fused epilogue (each warp has all 4 gates of its 8-h slice) ----
    const size_t COFF = (size_t)B_BATCH * H_DIM;

    const int h = h0 + wn * 8 + 2 * q;
    const float bF0 = bfv[h], bF1 = bfv[h + 1];
    const float bI0 = biv[h], bI1 = biv[h + 1];
    const float bO0 = bov[h], bO1 = bov[h + 1];
    const float bC0 = bcv[h], bC1 = bcv[h + 1];

    #pragma unroll
    for (int i = 0; i < 4; ++i) {
        #pragma unroll
        for (int hh = 0; hh < 2; ++hh) {
            const int row = m0 + wm * 64 + i * 16 + nr + 8 * hh;
            const int e = hh * 2;

            const float fg0 = sigmoidf_(acc[i][0][e]     + bF0);
            const float fg1 = sigmoidf_(acc[i][0][e + 1] + bF1);
            const float ig0 = sigmoidf_(acc[i][1][e]     + bI0);
            const float ig1 = sigmoidf_(acc[i][1][e + 1] + bI1);
            const float og0 = sigmoidf_(acc[i][2][e]     + bO0);
            const float og1 = sigmoidf_(acc[i][2][e + 1] + bO1);
            const float cg0 = tanhf(acc[i][3][e]     + bC0);
            const float cg1 = tanhf(acc[i][3][e + 1] + bC1);

            const float2 co = *reinterpret_cast<const float2*>(
                cold_p + (size_t)row * H_DIM + h);
            const float cn0 = fg0 * co.x + ig0 * cg0;
            const float cn1 = fg1 * co.y + ig1 * cg1;

            float2 hv; hv.x = og0 * tanhf(cn0); hv.y = og1 * tanhf(cn1);
            float2 cv; cv.x = cn0; cv.y = cn1;

            *reinterpret_cast<float2*>(out + (size_t)row * H_DIM + h)        = hv;
            *reinterpret_cast<float2*>(out + COFF + (size_t)row * H_DIM + h) = cv;
        }
    }
}

extern "C" void kernel_launch(void* const* d_in, const int* in_sizes, int n_in,
                              void* d_out, int out_size) {
    (void)in_sizes; (void)n_in; (void)out_size;
    const float* inputs = (const float*)d_in[0];
    const float* hidden = (const float*)d_in[1];
    const float* c      = (const float*)d_in[2];
    const float* Wf     = (const float*)d_in[3];
    const float* bf     = (const float*)d_in[4];
    const float* Wi     = (const float*)d_in[5];
    const float* bi     = (const float*)d_in[6];
    const float* Wo     = (const float*)d_in[7];
    const float* bo     = (const float*)d_in[8];
    const float* Wc     = (const float*)d_in[9];
    const float* bc     = (const float*)d_in[10];
    float* out = (float*)d_out;

    cvt_all_kernel<<<X_BLOCKS + W_BLOCKS, 256>>>(hidden, inputs, Wf, Wi, Wo, Wc);

    cudaFuncSetAttribute(lstm_cell_kernel,
                         cudaFuncAttributeMaxDynamicSharedMemorySize, SMEM_BYTES);
    dim3 grid(B_BATCH / TM, (4 * H_DIM) / NEFF);  // 64 x 32 = 2048 CTAs
    lstm_cell_kernel<<<grid, THREADS, SMEM_BYTES>>>(c, bf, bi, bo, bc, out);
}

// round 15
// speedup vs baseline: 1.1225x; 1.0968x over previous
#include <cuda_runtime.h>
#include <cuda_fp16.h>
#include <cstdint>

// Problem constants
#define B_BATCH 8192
#define H_DIM   1024
#define K_TOT   2048

// GEMM tiling: CTA = M128 x N128 (32 h-cols x 4 gates), 8 warps, 64x32 warp tile,
// 2 CTAs/SM + cross-chunk fragment pipelining + ldmatrix fragment loads.
#define TM      128
#define NEFF    128
#define KC      64               // K chunk in halves (128B rows)
#define NKT     (K_TOT / KC)     // 32 chunks
#define STAGES  3
#define KCP     72               // padded SMEM row stride in halves (144B)
#define THREADS 256

// SMEM offsets in halves
#define STAGE_HALVES  ((TM + NEFF) * KCP)          // 256*72 = 18432
#define A_OFF(st)     ((st) * STAGE_HALVES)
#define B_OFF(st)     ((st) * STAGE_HALVES + TM * KCP)
#define SMEM_BYTES    (STAGES * STAGE_HALVES * 2)  // 110592 -> 2 CTAs/SM

// fp16 scratch (conversion prologue, each launch)
__device__ __half g_xh[(size_t)B_BATCH * K_TOT];   // [8192, 2048] = [hidden|inputs]
__device__ __half g_wh[(size_t)4 * H_DIM * K_TOT]; // gate-interleaved rows, K-major

#define X_BLOCKS ((B_BATCH * K_TOT / 8) / 256)     // 8192
#define W_BLOCKS ((4 * H_DIM * K_TOT / 8) / 256)   // 4096

__device__ __forceinline__ void mma16816(float* c,
                                         uint32_t a0, uint32_t a1, uint32_t a2, uint32_t a3,
                                         uint32_t b0, uint32_t b1) {
    asm volatile(
        "mma.sync.aligned.m16n8k16.row.col.f32.f16.f16.f32 "
        "{%0,%1,%2,%3}, {%4,%5,%6,%7}, {%8,%9}, {%0,%1,%2,%3};"
        : "+f"(c[0]), "+f"(c[1]), "+f"(c[2]), "+f"(c[3])
        : "r"(a0), "r"(a1), "r"(a2), "r"(a3), "r"(b0), "r"(b1));
}

__device__ __forceinline__ void ldsm_x4(uint32_t& r0, uint32_t& r1,
                                        uint32_t& r2, uint32_t& r3, uint32_t addr) {
    asm volatile("ldmatrix.sync.aligned.m8n8.x4.shared.b16 {%0,%1,%2,%3}, [%4];"
                 : "=r"(r0), "=r"(r1), "=r"(r2), "=r"(r3) : "r"(addr));
}

__device__ __forceinline__ void cp16(uint32_t dst, const void* src) {
    asm volatile("cp.async.cg.shared.global [%0], [%1], 16;" :: "r"(dst), "l"(src));
}

__device__ __forceinline__ uint32_t smem_u32(const void* p) {
    uint32_t a;
    asm("{ .reg .u64 t; cvta.to.shared.u64 t, %1; cvt.u32.u64 %0, t; }" : "=r"(a) : "l"(p));
    return a;
}

__device__ __forceinline__ float sigmoidf_(float x) {
    return 1.0f / (1.0f + __expf(-x));
}

// ---------------- fused fp16 conversion prologue ----------------
// blocks [0, X_BLOCKS): x = [hidden|inputs]; blocks [X_BLOCKS, +W_BLOCKS): W permute
__global__ __launch_bounds__(256) void cvt_all_kernel(const float* __restrict__ hidden,
                                                      const float* __restrict__ inputs,
                                                      const float* __restrict__ Wf,
                                                      const float* __restrict__ Wi,
                                                      const float* __restrict__ Wo,
                                                      const float* __restrict__ Wc) {
    if (blockIdx.x < X_BLOCKS) {
        const size_t i = (size_t)blockIdx.x * blockDim.x + threadIdx.x;
        const size_t base = i * 8;
        const int r = (int)(base >> 11);
        const int c = (int)(base & 2047);
        const float* src = (c < H_DIM) ? (hidden + (size_t)r * H_DIM + c)
                                       : (inputs + (size_t)r * H_DIM + (c - H_DIM));
        float4 v0 = *reinterpret_cast<const float4*>(src);
        float4 v1 = *reinterpret_cast<const float4*>(src + 4);
        __half2 h[4];
        h[0] = __floats2half2_rn(v0.x, v0.y);
        h[1] = __floats2half2_rn(v0.z, v0.w);
        h[2] = __floats2half2_rn(v1.x, v1.y);
        h[3] = __floats2half2_rn(v1.z, v1.w);
        *reinterpret_cast<uint4*>(&g_xh[base]) = *reinterpret_cast<uint4*>(h);
    } else {
        // W rows permuted: n = (h>>5)*128 + ((h>>3)&3)*32 + g*8 + (h&7)
        const size_t i = (size_t)(blockIdx.x - X_BLOCKS) * blockDim.x + threadIdx.x;
        const size_t base = i * 8;
        const int g   = (int)(base >> 21);
        const size_t rem = base & ((1u << 21) - 1);
        const int h = (int)(rem >> 11);
        const int k = (int)(rem & 2047);
        const float* wp = (g == 0) ? Wf : (g == 1) ? Wi : (g == 2) ? Wo : Wc;
        const float* src = wp + (size_t)h * K_TOT + k;
        float4 v0 = *reinterpret_cast<const float4*>(src);
        float4 v1 = *reinterpret_cast<const float4*>(src + 4);
        __half2 hh[4];
        hh[0] = __floats2half2_rn(v0.x, v0.y);
        hh[1] = __floats2half2_rn(v0.z, v0.w);
        hh[2] = __floats2half2_rn(v1.x, v1.y);
        hh[3] = __floats2half2_rn(v1.z, v1.w);
        const int n = (h >> 5) * 128 + ((h >> 3) & 3) * 32 + g * 8 + (h & 7);
        *reinterpret_cast<uint4*>(&g_wh[(size_t)n * K_TOT + k]) = *reinterpret_cast<uint4*>(hh);
    }
}

// ---------------- fused GEMM + LSTM epilogue ----------------

__global__ __launch_bounds__(THREADS, 2)
void lstm_cell_kernel(const float* __restrict__ cold_p,
                      const float* __restrict__ bfv, const float* __restrict__ biv,
                      const float* __restrict__ bov, const float* __restrict__ bcv,
                      float* __restrict__ out) {
    extern __shared__ __half sh[];
    const uint32_t sbase = smem_u32(sh);

    const int tid  = threadIdx.x;
    const int lane = tid & 31;
    const int wid  = tid >> 5;
    const int wm   = wid & 1;    // 2 warps along M (64 rows each)
    const int wn   = wid >> 1;   // 4 warps along N_eff (32 each)
    const int m0   = blockIdx.x * TM;
    const int n0   = blockIdx.y * NEFF;
    const int h0   = blockIdx.y * 32;

    const int f  = tid & 7;      // 16B chunk within a 128B row
    const int rb = tid >> 3;     // 0..31

    // ldmatrix per-lane base offsets (bytes, within a stage)
    // A x4 (i-block): row = wm*64 + i*16 + (lane&15), col8 = (lane>>4)*8
    const uint32_t a_lane_off =
        2u * ((uint32_t)(wm * 64 + (lane & 15)) * KCP + ((lane >> 4) << 3));
    // B x4 (j-pair jp): n-row = wn*32 + jp*16 + (lane>>4)*8 + (lane&7), col8 = lane&8
    const uint32_t b_lane_off =
        2u * ((uint32_t)(wn * 32 + ((lane >> 4) << 3) + (lane & 7)) * KCP + (lane & 8));

    // acc[i][j][e]: i = m-block (16 rows), j = gate (8 cols)
    float acc[4][4][4];
    #pragma unroll
    for (int i = 0; i < 4; ++i)
        #pragma unroll
        for (int j = 0; j < 4; ++j)
            #pragma unroll
            for (int e = 0; e < 4; ++e)
                acc[i][j][e] = 0.0f;

#define ISSUE(kt_, st_)                                                                  \
    do {                                                                                 \
        if ((kt_) < NKT) {                                                               \
            const int kb_ = (kt_) * KC;                                                  \
            _Pragma("unroll")                                                            \
            for (int p = 0; p < 4; ++p) {                                                \
                const int r_ = rb + 32 * p;                                              \
                cp16(sbase + 2u * (A_OFF(st_) + r_ * KCP + f * 8),                       \
                     &g_xh[(size_t)(m0 + r_) * K_TOT + kb_ + f * 8]);                    \
            }                                                                            \
            _Pragma("unroll")                                                            \
            for (int p = 0; p < 4; ++p) {                                                \
                const int r_ = rb + 32 * p;                                              \
                cp16(sbase + 2u * (B_OFF(st_) + r_ * KCP + f * 8),                       \
                     &g_wh[(size_t)(n0 + r_) * K_TOT + kb_ + f * 8]);                    \
            }                                                                            \
        }                                                                                \
        asm volatile("cp.async.commit_group;");                                          \
    } while (0)

    // Register fragment double buffers: 32 + 16 regs
    uint32_t af[2][4][4];
    uint32_t bfr[2][4][2];

    // ldmatrix fragment loads: 4 A-x4 + 2 B-x4 per k-step (was 24 LDS.32)
#define LOAD_FRAGS(st_, s_, bu_)                                                         \
    do {                                                                                 \
        const uint32_t abase_ = sbase + 2u * A_OFF(st_) + a_lane_off + (s_) * 32u;       \
        const uint32_t bbase_ = sbase + 2u * B_OFF(st_) + b_lane_off + (s_) * 32u;       \
        _Pragma("unroll")                                                                \
        for (int i = 0; i < 4; ++i)                                                      \
            ldsm_x4(af[bu_][i][0], af[bu_][i][1], af[bu_][i][2], af[bu_][i][3],          \
                    abase_ + (uint32_t)i * (16u * KCP * 2u));                            \
        _Pragma("unroll")                                                                \
        for (int jp = 0; jp < 2; ++jp)                                                   \
            ldsm_x4(bfr[bu_][2 * jp][0], bfr[bu_][2 * jp][1],                            \
                    bfr[bu_][2 * jp + 1][0], bfr[bu_][2 * jp + 1][1],                    \
                    bbase_ + (uint32_t)jp * (16u * KCP * 2u));                           \
    } while (0)

#define MMA_STEP(bu_)                                                                    \
    do {                                                                                 \
        _Pragma("unroll")                                                                \
        for (int i = 0; i < 4; ++i)                                                      \
            _Pragma("unroll")                                                            \
            for (int j = 0; j < 4; ++j)                                                  \
                mma16816(acc[i][j], af[bu_][i][0], af[bu_][i][1],                        \
                         af[bu_][i][2], af[bu_][i][3], bfr[bu_][j][0], bfr[bu_][j][1]);  \
    } while (0)

    // ---- 3-stage pipeline, cross-chunk frag prefetch, mid-chunk barrier ----
    ISSUE(0, 0);
    ISSUE(1, 1);
    asm volatile("cp.async.wait_group 1;");      // stage 0 landed
    __syncthreads();                             // visible to all threads
    LOAD_FRAGS(0, 0, 0);                         // chunk 0, step 0 -> buf0

    for (int kt = 0; kt < NKT; ++kt) {
        const int st  = kt % STAGES;
        const int stn = (kt + 1) % STAGES;

        LOAD_FRAGS(st, 1, 1);                    // step 1 -> buf1
        MMA_STEP(0);                             // consume step 0 (buf0)

        asm volatile("cp.async.wait_group 0;");  // stage kt+1 landed (own groups)
        __syncthreads();                         // all threads past kt-1 reads
        ISSUE(kt + 2, (kt + 2) % STAGES);        // refill stage freed by chunk kt-1

        LOAD_FRAGS(st, 2, 0);                    // step 2 -> buf0
        MMA_STEP(1);                             // consume step 1 (buf1)
        LOAD_FRAGS(st, 3, 1);                    // step 3 -> buf1
        MMA_STEP(0);                             // consume step 2 (buf0)
        LOAD_FRAGS(stn, 0, 0);                   // next chunk step 0 -> buf0
        MMA_STEP(1);                             // consume step 3 (buf1)
    }

    // ---- fused epilogue (each warp has all 4 gates of its 8-h slice) ----
    const size_t COFF = (size_t)B_BATCH * H_DIM;
    const int q  = lane & 3;
    const int nr = lane >> 2;

    const int h = h0 + wn * 8 + 2 * q;
    const float bF0 = bfv[h], bF1 = bfv[h + 1];
    const float bI0 = biv[h], bI1 = biv[h + 1];
    const float bO0 = bov[h], bO1 = bov[h + 1];
    const float bC0 = bcv[h], bC1 = bcv[h + 1];

    #pragma unroll
    for (int i = 0; i < 4; ++i) {
        #pragma unroll
        for (int hh = 0; hh < 2; ++hh) {
            const int row = m0 + wm * 64 + i * 16 + nr + 8 * hh;
            const int e = hh * 2;

            const float fg0 = sigmoidf_(acc[i][0][e]     + bF0);
            const float fg1 = sigmoidf_(acc[i][0][e + 1] + bF1);
            const float ig0 = sigmoidf_(acc[i][1][e]     + bI0);
            const float ig1 = sigmoidf_(acc[i][1][e + 1] + bI1);
            const float og0 = sigmoidf_(acc[i][2][e]     + bO0);
            const float og1 = sigmoidf_(acc[i][2][e + 1] + bO1);
            const float cg0 = tanhf(acc[i][3][e]     + bC0);
            const float cg1 = tanhf(acc[i][3][e + 1] + bC1);

            const float2 co = *reinterpret_cast<const float2*>(
                cold_p + (size_t)row * H_DIM + h);
            const float cn0 = fg0 * co.x + ig0 * cg0;
            const float cn1 = fg1 * co.y + ig1 * cg1;

            float2 hv; hv.x = og0 * tanhf(cn0); hv.y = og1 * tanhf(cn1);
            float2 cv; cv.x = cn0; cv.y = cn1;

            *reinterpret_cast<float2*>(out + (size_t)row * H_DIM + h)        = hv;
            *reinterpret_cast<float2*>(out + COFF + (size_t)row * H_DIM + h) = cv;
        }
    }
}

extern "C" void kernel_launch(void* const* d_in, const int* in_sizes, int n_in,
                              void* d_out, int out_size) {
    (void)in_sizes; (void)n_in; (void)out_size;
    const float* inputs = (const float*)d_in[0];
    const float* hidden = (const float*)d_in[1];
    const float* c      = (const float*)d_in[2];
    const float* Wf     = (const float*)d_in[3];
    const float* bf     = (const float*)d_in[4];
    const float* Wi     = (const float*)d_in[5];
    const float* bi     = (const float*)d_in[6];
    const float* Wo     = (const float*)d_in[7];
    const float* bo     = (const float*)d_in[8];
    const float* Wc     = (const float*)d_in[9];
    const float* bc     = (const float*)d_in[10];
    float* out = (float*)d_out;

    cvt_all_kernel<<<X_BLOCKS + W_BLOCKS, 256>>>(hidden, inputs, Wf, Wi, Wo, Wc);

    cudaFuncSetAttribute(lstm_cell_kernel,
                         cudaFuncAttributeMaxDynamicSharedMemorySize, SMEM_BYTES);
    dim3 grid(B_BATCH / TM, (4 * H_DIM) / NEFF);  // 64 x 32 = 2048 CTAs
    lstm_cell_kernel<<<grid, THREADS, SMEM_BYTES>>>(c, bf, bi, bo, bc, out);
}

// round 16
// speedup vs baseline: 1.1397x; 1.0153x over previous
#include <cuda_runtime.h>
#include <cuda_fp16.h>
#include <cstdint>

// Problem constants
#define B_BATCH 8192
#define H_DIM   1024
#define K_TOT   2048

// GEMM tiling: CTA = M128 x N128, 4 warps (2x2), warp tile 64x64, 2 CTAs/SM,
// ldmatrix fragment loads + cross-chunk fragment pipelining.
#define TM      128
#define NEFF    128
#define KC      64               // K chunk in halves (128B rows)
#define NKT     (K_TOT / KC)     // 32 chunks
#define STAGES  3
#define KCP     72               // padded SMEM row stride in halves (144B)
#define THREADS 128

// SMEM offsets in halves
#define STAGE_HALVES  ((TM + NEFF) * KCP)          // 256*72 = 18432
#define A_OFF(st)     ((st) * STAGE_HALVES)
#define B_OFF(st)     ((st) * STAGE_HALVES + TM * KCP)
#define SMEM_BYTES    (STAGES * STAGE_HALVES * 2)  // 110592 -> 2 CTAs/SM

// fp16 scratch (conversion prologue, each launch)
__device__ __half g_xh[(size_t)B_BATCH * K_TOT];   // [8192, 2048] = [hidden|inputs]
__device__ __half g_wh[(size_t)4 * H_DIM * K_TOT]; // gate-interleaved rows, K-major

#define X_BLOCKS ((B_BATCH * K_TOT / 8) / 256)     // 8192
#define W_BLOCKS ((4 * H_DIM * K_TOT / 8) / 256)   // 4096

__device__ __forceinline__ void mma16816(float* c,
                                         uint32_t a0, uint32_t a1, uint32_t a2, uint32_t a3,
                                         uint32_t b0, uint32_t b1) {
    asm volatile(
        "mma.sync.aligned.m16n8k16.row.col.f32.f16.f16.f32 "
        "{%0,%1,%2,%3}, {%4,%5,%6,%7}, {%8,%9}, {%0,%1,%2,%3};"
        : "+f"(c[0]), "+f"(c[1]), "+f"(c[2]), "+f"(c[3])
        : "r"(a0), "r"(a1), "r"(a2), "r"(a3), "r"(b0), "r"(b1));
}

__device__ __forceinline__ void ldsm_x4(uint32_t& r0, uint32_t& r1,
                                        uint32_t& r2, uint32_t& r3, uint32_t addr) {
    asm volatile("ldmatrix.sync.aligned.m8n8.x4.shared.b16 {%0,%1,%2,%3}, [%4];"
                 : "=r"(r0), "=r"(r1), "=r"(r2), "=r"(r3) : "r"(addr));
}

__device__ __forceinline__ void cp16(uint32_t dst, const void* src) {
    asm volatile("cp.async.cg.shared.global [%0], [%1], 16;" :: "r"(dst), "l"(src));
}

__device__ __forceinline__ uint32_t smem_u32(const void* p) {
    uint32_t a;
    asm("{ .reg .u64 t; cvta.to.shared.u64 t, %1; cvt.u32.u64 %0, t; }" : "=r"(a) : "l"(p));
    return a;
}

__device__ __forceinline__ float sigmoidf_(float x) {
    return 1.0f / (1.0f + __expf(-x));
}

// ---------------- fused fp16 conversion prologue ----------------
// blocks [0, X_BLOCKS): x = [hidden|inputs]; blocks [X_BLOCKS, +W_BLOCKS): W permute
__global__ __launch_bounds__(256) void cvt_all_kernel(const float* __restrict__ hidden,
                                                      const float* __restrict__ inputs,
                                                      const float* __restrict__ Wf,
                                                      const float* __restrict__ Wi,
                                                      const float* __restrict__ Wo,
                                                      const float* __restrict__ Wc) {
    if (blockIdx.x < X_BLOCKS) {
        const size_t i = (size_t)blockIdx.x * blockDim.x + threadIdx.x;
        const size_t base = i * 8;
        const int r = (int)(base >> 11);
        const int c = (int)(base & 2047);
        const float* src = (c < H_DIM) ? (hidden + (size_t)r * H_DIM + c)
                                       : (inputs + (size_t)r * H_DIM + (c - H_DIM));
        float4 v0 = *reinterpret_cast<const float4*>(src);
        float4 v1 = *reinterpret_cast<const float4*>(src + 4);
        __half2 h[4];
        h[0] = __floats2half2_rn(v0.x, v0.y);
        h[1] = __floats2half2_rn(v0.z, v0.w);
        h[2] = __floats2half2_rn(v1.x, v1.y);
        h[3] = __floats2half2_rn(v1.z, v1.w);
        *reinterpret_cast<uint4*>(&g_xh[base]) = *reinterpret_cast<uint4*>(h);
    } else {
        // W rows permuted: each warp's 64 n-cols = 4 gates x 16 h:
        // n = (h>>5)*128 + ((h>>4)&1)*64 + g*16 + (h&15)
        const size_t i = (size_t)(blockIdx.x - X_BLOCKS) * blockDim.x + threadIdx.x;
        const size_t base = i * 8;
        const int g   = (int)(base >> 21);
        const size_t rem = base & ((1u << 21) - 1);
        const int h = (int)(rem >> 11);
        const int k = (int)(rem & 2047);
        const float* wp = (g == 0) ? Wf : (g == 1) ? Wi : (g == 2) ? Wo : Wc;
        const float* src = wp + (size_t)h * K_TOT + k;
        float4 v0 = *reinterpret_cast<const float4*>(src);
        float4 v1 = *reinterpret_cast<const float4*>(src + 4);
        __half2 hh[4];
        hh[0] = __floats2half2_rn(v0.x, v0.y);
        hh[1] = __floats2half2_rn(v0.z, v0.w);
        hh[2] = __floats2half2_rn(v1.x, v1.y);
        hh[3] = __floats2half2_rn(v1.z, v1.w);
        const int n = (h >> 5) * 128 + ((h >> 4) & 1) * 64 + g * 16 + (h & 15);
        *reinterpret_cast<uint4*>(&g_wh[(size_t)n * K_TOT + k]) = *reinterpret_cast<uint4*>(hh);
    }
}

// ---------------- fused GEMM + LSTM epilogue ----------------

__global__ __launch_bounds__(THREADS, 2)
void lstm_cell_kernel(const float* __restrict__ cold_p,
                      const float* __restrict__ bfv, const float* __restrict__ biv,
                      const float* __restrict__ bov, const float* __restrict__ bcv,
                      float* __restrict__ out) {
    extern __shared__ __half sh[];
    const uint32_t sbase = smem_u32(sh);

    const int tid  = threadIdx.x;
    const int lane = tid & 31;
    const int wid  = tid >> 5;
    const int wm   = wid & 1;    // 2 warps along M (64 rows each)
    const int wn   = wid >> 1;   // 2 warps along N_eff (64 each)
    const int m0   = blockIdx.x * TM;
    const int n0   = blockIdx.y * NEFF;
    const int h0   = blockIdx.y * 32;

    const int f  = tid & 7;      // 16B chunk within a 128B row
    const int rb = tid >> 3;     // 0..15

    // ldmatrix per-lane base offsets (bytes, within a stage)
    // A x4 (i-block): row = wm*64 + i*16 + (lane&15), col8 = (lane>>4)*8
    const uint32_t a_lane_off =
        2u * ((uint32_t)(wm * 64 + (lane & 15)) * KCP + ((lane >> 4) << 3));
    // B x4 (j-pair jp): n-row = wn*64 + jp*16 + (lane>>4)*8 + (lane&7), col8 = lane&8
    const uint32_t b_lane_off =
        2u * ((uint32_t)(wn * 64 + ((lane >> 4) << 3) + (lane & 7)) * KCP + (lane & 8));

    // acc[i][j][e]: 64x64 warp tile, i = m-block (16 rows), j = n-block (8 cols)
    float acc[4][8][4];
    #pragma unroll
    for (int i = 0; i < 4; ++i)
        #pragma unroll
        for (int j = 0; j < 8; ++j)
            #pragma unroll
            for (int e = 0; e < 4; ++e)
                acc[i][j][e] = 0.0f;

#define ISSUE(kt_, st_)                                                                  \
    do {                                                                                 \
        if ((kt_) < NKT) {                                                               \
            const int kb_ = (kt_) * KC;                                                  \
            _Pragma("unroll")                                                            \
            for (int p = 0; p < 8; ++p) {                                                \
                const int r_ = rb + 16 * p;                                              \
                cp16(sbase + 2u * (A_OFF(st_) + r_ * KCP + f * 8),                       \
                     &g_xh[(size_t)(m0 + r_) * K_TOT + kb_ + f * 8]);                    \
            }                                                                            \
            _Pragma("unroll")                                                            \
            for (int p = 0; p < 8; ++p) {                                                \
                const int r_ = rb + 16 * p;                                              \
                cp16(sbase + 2u * (B_OFF(st_) + r_ * KCP + f * 8),                       \
                     &g_wh[(size_t)(n0 + r_) * K_TOT + kb_ + f * 8]);                    \
            }                                                                            \
        }                                                                                \
        asm volatile("cp.async.commit_group;");                                          \
    } while (0)

    // Register fragment double buffers: 32 + 32 regs
    uint32_t af[2][4][4];
    uint32_t bfr[2][8][2];

    // ldmatrix fragment loads: 4 A-x4 + 4 B-x4 per k-step
#define LOAD_FRAGS(st_, s_, bu_)                                                         \
    do {                                                                                 \
        const uint32_t abase_ = sbase + 2u * A_OFF(st_) + a_lane_off + (s_) * 32u;       \
        const uint32_t bbase_ = sbase + 2u * B_OFF(st_) + b_lane_off + (s_) * 32u;       \
        _Pragma("unroll")                                                                \
        for (int i = 0; i < 4; ++i)                                                      \
            ldsm_x4(af[bu_][i][0], af[bu_][i][1], af[bu_][i][2], af[bu_][i][3],          \
                    abase_ + (uint32_t)i * (16u * KCP * 2u));                            \
        _Pragma("unroll")                                                                \
        for (int jp = 0; jp < 4; ++jp)                                                   \
            ldsm_x4(bfr[bu_][2 * jp][0], bfr[bu_][2 * jp][1],                            \
                    bfr[bu_][2 * jp + 1][0], bfr[bu_][2 * jp + 1][1],                    \
                    bbase_ + (uint32_t)jp * (16u * KCP * 2u));                           \
    } while (0)

#define MMA_STEP(bu_)                                                                    \
    do {                                                                                 \
        _Pragma("unroll")                                                                \
        for (int i = 0; i < 4; ++i)                                                      \
            _Pragma("unroll")                                                            \
            for (int j = 0; j < 8; ++j)                                                  \
                mma16816(acc[i][j], af[bu_][i][0], af[bu_][i][1],                        \
                         af[bu_][i][2], af[bu_][i][3], bfr[bu_][j][0], bfr[bu_][j][1]);  \
    } while (0)

    // ---- 3-stage pipeline, cross-chunk frag prefetch, mid-chunk barrier ----
    //
    // Invariants at top of chunk kt:
    //   * stage kt resident & visible; step-0 frags of chunk kt in buf0
    //   * cp.async group for stage kt+1 issued (completes during this chunk)
    // Mid-chunk: wait_group 0 + barrier, then ISSUE(kt+2) overwrites stage
    // (kt+2)%3 = (kt-1)%3, whose reads all ended before this barrier.
    ISSUE(0, 0);
    ISSUE(1, 1);
    asm volatile("cp.async.wait_group 1;");      // stage 0 landed
    __syncthreads();                             // visible to all threads
    LOAD_FRAGS(0, 0, 0);                         // chunk 0, step 0 -> buf0

    for (int kt = 0; kt < NKT; ++kt) {
        const int st  = kt % STAGES;
        const int stn = (kt + 1) % STAGES;

        LOAD_FRAGS(st, 1, 1);                    // step 1 -> buf1
        MMA_STEP(0);                             // consume step 0 (buf0)

        asm volatile("cp.async.wait_group 0;");  // stage kt+1 landed
        __syncthreads();                         // all threads past kt-1 reads
        ISSUE(kt + 2, (kt + 2) % STAGES);        // refill stage freed by chunk kt-1

        LOAD_FRAGS(st, 2, 0);                    // step 2 -> buf0
        MMA_STEP(1);                             // consume step 1 (buf1)
        LOAD_FRAGS(st, 3, 1);                    // step 3 -> buf1
        MMA_STEP(0);                             // consume step 2 (buf0)
        LOAD_FRAGS(stn, 0, 0);                   // next chunk step 0 -> buf0
        MMA_STEP(1);                             // consume step 3 (buf1)
    }

    // ---- fused epilogue (each warp has all 4 gates of its 16-h slice) ----
    const size_t COFF = (size_t)B_BATCH * H_DIM;
    const int q  = lane & 3;
    const int nr = lane >> 2;

    #pragma unroll
    for (int jc = 0; jc < 2; ++jc) {
        const int h = h0 + wn * 16 + jc * 8 + 2 * q;
        const float bF0 = bfv[h], bF1 = bfv[h + 1];
        const float bI0 = biv[h], bI1 = biv[h + 1];
        const float bO0 = bov[h], bO1 = bov[h + 1];
        const float bC0 = bcv[h], bC1 = bcv[h + 1];

        #pragma unroll
        for (int i = 0; i < 4; ++i) {
            #pragma unroll
            for (int hh = 0; hh < 2; ++hh) {
                const int row = m0 + wm * 64 + i * 16 + nr + 8 * hh;
                const int e = hh * 2;

                const float fg0 = sigmoidf_(acc[i][0 + jc][e]     + bF0);
                const float fg1 = sigmoidf_(acc[i][0 + jc][e + 1] + bF1);
                const float ig0 = sigmoidf_(acc[i][2 + jc][e]     + bI0);
                const float ig1 = sigmoidf_(acc[i][2 + jc][e + 1] + bI1);
                const float og0 = sigmoidf_(acc[i][4 + jc][e]     + bO0);
                const float og1 = sigmoidf_(acc[i][4 + jc][e + 1] + bO1);
                const float cg0 = tanhf(acc[i][6 + jc][e]     + bC0);
                const float cg1 = tanhf(acc[i][6 + jc][e + 1] + bC1);

                const float2 co = *reinterpret_cast<const float2*>(
                    cold_p + (size_t)row * H_DIM + h);
                const float cn0 = fg0 * co.x + ig0 * cg0;
                const float cn1 = fg1 * co.y + ig1 * cg1;

                float2 hv; hv.x = og0 * tanhf(cn0); hv.y = og1 * tanhf(cn1);
                float2 cv; cv.x = cn0; cv.y = cn1;

                *reinterpret_cast<float2*>(out + (size_t)row * H_DIM + h)        = hv;
                *reinterpret_cast<float2*>(out + COFF + (size_t)row * H_DIM + h) = cv;
            }
        }
    }
}

extern "C" void kernel_launch(void* const* d_in, const int* in_sizes, int n_in,
                              void* d_out, int out_size) {
    (void)in_sizes; (void)n_in; (void)out_size;
    const float* inputs = (const float*)d_in[0];
    const float* hidden = (const float*)d_in[1];
    const float* c      = (const float*)d_in[2];
    const float* Wf     = (const float*)d_in[3];
    const float* bf     = (const float*)d_in[4];
    const float* Wi     = (const float*)d_in[5];
    const float* bi     = (const float*)d_in[6];
    const float* Wo     = (const float*)d_in[7];
    const float* bo     = (const float*)d_in[8];
    const float* Wc     = (const float*)d_in[9];
    const float* bc     = (const float*)d_in[10];
    float* out = (float*)d_out;

    cvt_all_kernel<<<X_BLOCKS + W_BLOCKS, 256>>>(hidden, inputs, Wf, Wi, Wo, Wc);

    cudaFuncSetAttribute(lstm_cell_kernel,
                         cudaFuncAttributeMaxDynamicSharedMemorySize, SMEM_BYTES);
    dim3 grid(B_BATCH / TM, (4 * H_DIM) / NEFF);  // 64 x 32 = 2048 CTAs
    lstm_cell_kernel<<<grid, THREADS, SMEM_BYTES>>>(c, bf, bi, bo, bc, out);
}